// round 17
// baseline (speedup 1.0000x reference)
#include <cuda_runtime.h>
#include <cuda_bf16.h>

#define NN 50000
#define EE 800000
#define DD 128
#define GG 64
#define MAXD 64
#define NEG_SLOPE 0.2f
#define HSPLIT 25024   // chunk boundary: multiple of 32 (gemm tile) and 8 (agg block)

// ---------------- scratch (zero-init at load; self-restoring per run) -------
__device__ float g_h[NN * DD];
__device__ float g_hWa[NN * DD];       // layer-1 projected features
__device__ float g_hWb[NN * DD];       // layer-2 projected features
__device__ float g_asa[NN], g_asb[NN];
__device__ float g_ada[NN], g_adb[NN];
__device__ int   g_dcnt[NN];
__device__ int   g_nbr[NN * MAXD];
__device__ float g_C1[DD * DD];        // folded lin_w @ w1
__device__ float g_c1[DD];             // folded lin_b @ w1
__device__ float g_psum[GG];
__device__ float g_cnt[GG];

__device__ __forceinline__ float lrelu(float x) {
    return x > 0.f ? x : NEG_SLOPE * x;
}

// ---------------- bucketed adjacency build (+ psum/cnt zeroing) -------------
__global__ void k_fill(const int* __restrict__ src, const int* __restrict__ dst) {
    int e = blockIdx.x * blockDim.x + threadIdx.x;
    if (blockIdx.x == 0 && threadIdx.x < GG) {
        g_psum[threadIdx.x] = 0.f;
        g_cnt[threadIdx.x] = 0.f;
    }
    if (e < EE) {
        int d = dst[e];
        int p = atomicAdd(&g_dcnt[d], 1);
        if (p < MAXD) g_nbr[d * MAXD + p] = src[e];
    }
}

// ---------------- weight fold: C1 = lin_w @ w1, c1 = lin_b @ w1 -------------
__global__ void k_wfold(const float* __restrict__ lin_w,
                        const float* __restrict__ lin_b,
                        const float* __restrict__ w1) {
    int b = blockIdx.x;
    int t = threadIdx.x;
    int col = t & 127;
    if (b < 64) {
        int row = b * 2 + (t >> 7);
        float acc = 0.f;
#pragma unroll 8
        for (int k = 0; k < DD; k++)
            acc = fmaf(lin_w[row * DD + k], w1[k * DD + col], acc);
        g_C1[row * DD + col] = acc;
    } else if (t < 128) {
        float acc = 0.f;
#pragma unroll 8
        for (int k = 0; k < DD; k++)
            acc = fmaf(lin_b[k], w1[k * DD + col], acc);
        g_c1[col] = acc;
    }
}

// ---------------- GEMM (R12 core) + fused alpha; row-range + buffer select --
__global__ void __launch_bounds__(128) k_gemm(
        const float* __restrict__ Aext, int useExt,
        const float* __restrict__ W,
        const float* __restrict__ bias, int addBias,
        const float* __restrict__ a_src, const float* __restrict__ a_dst,
        int rowStart, int outSel) {
    __shared__ float Ws[64 * DD];    // 32 KB
    __shared__ float As[32][DD];     // 16 KB

    const float* __restrict__ A = useExt ? Aext : g_h;
    float* __restrict__ C  = outSel ? g_hWb : g_hWa;
    float* __restrict__ AS = outSel ? g_asb : g_asa;
    float* __restrict__ AD = outSel ? g_adb : g_ada;

    int tid = threadIdx.x;
    int row0 = rowStart + blockIdx.x * 32;

#pragma unroll
    for (int i = 0; i < 8; i++) {
        int slot = tid + i * 128;
        int r = slot >> 5;
        int c4 = (slot & 31) << 2;
        int gr = row0 + r;
        float4 v = make_float4(0.f, 0.f, 0.f, 0.f);
        if (gr < NN) v = *(const float4*)&A[gr * DD + c4];
        *(float4*)&As[r][c4] = v;
    }

    int warp = tid >> 5, lane = tid & 31;
    int r0 = warp << 3;
    int c = lane << 2;

    float4 acc[8];
#pragma unroll
    for (int r = 0; r < 8; r++) acc[r] = make_float4(0.f, 0.f, 0.f, 0.f);

    for (int kb = 0; kb < 2; kb++) {
        __syncthreads();
#pragma unroll
        for (int i = 0; i < 16; i++) {
            int slot = tid + i * 128;
            *(float4*)&Ws[slot * 4] = *(const float4*)&W[kb * 64 * DD + slot * 4];
        }
        __syncthreads();
#pragma unroll 4
        for (int kq = 0; kq < 16; kq++) {
            int kc = kb * 64 + kq * 4;
            float4 a[8];
#pragma unroll
            for (int r = 0; r < 8; r++)
                a[r] = *(const float4*)&As[r0 + r][kc];
#pragma unroll
            for (int j = 0; j < 4; j++) {
                float4 b = *(const float4*)&Ws[(kq * 4 + j) * DD + c];
#pragma unroll
                for (int r = 0; r < 8; r++) {
                    float av = (j == 0) ? a[r].x : (j == 1) ? a[r].y
                             : (j == 2) ? a[r].z : a[r].w;
                    acc[r].x = fmaf(av, b.x, acc[r].x);
                    acc[r].y = fmaf(av, b.y, acc[r].y);
                    acc[r].z = fmaf(av, b.z, acc[r].z);
                    acc[r].w = fmaf(av, b.w, acc[r].w);
                }
            }
        }
    }

    float4 bv = make_float4(0, 0, 0, 0);
    if (addBias) bv = *(const float4*)&bias[c];
    float4 sv = *(const float4*)&a_src[c];
    float4 dv = *(const float4*)&a_dst[c];

#pragma unroll
    for (int r = 0; r < 8; r++) {
        float4 o = acc[r];
        o.x += bv.x; o.y += bv.y; o.z += bv.z; o.w += bv.w;
        int gr = row0 + r0 + r;
        if (gr < NN) *(float4*)&C[gr * DD + c] = o;

        float ps = o.x * sv.x + o.y * sv.y + o.z * sv.z + o.w * sv.w;
        float pd = o.x * dv.x + o.y * dv.y + o.z * dv.z + o.w * dv.w;
#pragma unroll
        for (int of = 16; of; of >>= 1) {
            ps += __shfl_xor_sync(0xffffffffu, ps, of);
            pd += __shfl_xor_sync(0xffffffffu, pd, of);
        }
        if (lane == 0 && gr < NN) {
            AS[gr] = ps;
            AD[gr] = pd;
        }
    }
}

// ---------------- GAT agg (R13 core); node-range + buffer select ------------
__global__ void k_agg(const float* __restrict__ bias,
                      const int* __restrict__ batch, int doPool,
                      const float* __restrict__ out_w,
                      int nodeStart, int inSel) {
    int node = nodeStart + blockIdx.x * 8 + (threadIdx.x >> 5);
    int lane = threadIdx.x & 31;
    if (node >= NN) return;

    const float* __restrict__ hW = inSel ? g_hWb : g_hWa;
    const float* __restrict__ AS = inSel ? g_asb : g_asa;
    const float* __restrict__ AD = inSel ? g_adb : g_ada;

    int deg = g_dcnt[node];
    if (deg > MAXD) deg = MAXD;
    int base = node * MAXD;
    if (doPool && lane == 0) g_dcnt[node] = 0;   // restore for next replay

    float adi = AD[node];
    float eself = lrelu(AS[node] + adi);

    int j0 = (lane < deg)      ? g_nbr[base + lane]      : -1;
    int j1 = (lane + 32 < deg) ? g_nbr[base + lane + 32] : -1;
    float e0 = (j0 >= 0) ? lrelu(AS[j0] + adi) : -3.4e38f;
    float e1 = (j1 >= 0) ? lrelu(AS[j1] + adi) : -3.4e38f;

    float m = fmaxf(eself, fmaxf(e0, e1));
#pragma unroll
    for (int o = 16; o; o >>= 1)
        m = fmaxf(m, __shfl_xor_sync(0xffffffffu, m, o));

    float w0 = (j0 >= 0) ? __expf(e0 - m) : 0.f;
    float w1 = (j1 >= 0) ? __expf(e1 - m) : 0.f;
    float ssum = w0 + w1;
#pragma unroll
    for (int o = 16; o; o >>= 1)
        ssum += __shfl_xor_sync(0xffffffffu, ssum, o);
    float wself = __expf(eself - m);
    ssum += wself;

    int c = lane << 2;
    float4 hv = *(const float4*)&hW[node * DD + c];
    float4 acc0 = make_float4(wself * hv.x, wself * hv.y, wself * hv.z, wself * hv.w);
    float4 acc1 = make_float4(0.f, 0.f, 0.f, 0.f);

    int n0 = deg < 32 ? deg : 32;
    int i = 0;
    for (; i + 2 <= n0; i += 2) {
        int ja = __shfl_sync(0xffffffffu, j0, i);
        int jb = __shfl_sync(0xffffffffu, j0, i + 1);
        float wa = __shfl_sync(0xffffffffu, w0, i);
        float wb = __shfl_sync(0xffffffffu, w0, i + 1);
        float4 va = *(const float4*)&hW[ja * DD + c];
        float4 vb = *(const float4*)&hW[jb * DD + c];
        acc0.x = fmaf(wa, va.x, acc0.x); acc0.y = fmaf(wa, va.y, acc0.y);
        acc0.z = fmaf(wa, va.z, acc0.z); acc0.w = fmaf(wa, va.w, acc0.w);
        acc1.x = fmaf(wb, vb.x, acc1.x); acc1.y = fmaf(wb, vb.y, acc1.y);
        acc1.z = fmaf(wb, vb.z, acc1.z); acc1.w = fmaf(wb, vb.w, acc1.w);
    }
    if (i < n0) {
        int ja = __shfl_sync(0xffffffffu, j0, i);
        float wa = __shfl_sync(0xffffffffu, w0, i);
        float4 va = *(const float4*)&hW[ja * DD + c];
        acc0.x = fmaf(wa, va.x, acc0.x); acc0.y = fmaf(wa, va.y, acc0.y);
        acc0.z = fmaf(wa, va.z, acc0.z); acc0.w = fmaf(wa, va.w, acc0.w);
    }
    i = 32;
    for (; i + 2 <= deg; i += 2) {
        int ja = __shfl_sync(0xffffffffu, j1, i - 32);
        int jb = __shfl_sync(0xffffffffu, j1, i - 31);
        float wa = __shfl_sync(0xffffffffu, w1, i - 32);
        float wb = __shfl_sync(0xffffffffu, w1, i - 31);
        float4 va = *(const float4*)&hW[ja * DD + c];
        float4 vb = *(const float4*)&hW[jb * DD + c];
        acc0.x = fmaf(wa, va.x, acc0.x); acc0.y = fmaf(wa, va.y, acc0.y);
        acc0.z = fmaf(wa, va.z, acc0.z); acc0.w = fmaf(wa, va.w, acc0.w);
        acc1.x = fmaf(wb, vb.x, acc1.x); acc1.y = fmaf(wb, vb.y, acc1.y);
        acc1.z = fmaf(wb, vb.z, acc1.z); acc1.w = fmaf(wb, vb.w, acc1.w);
    }
    if (i < deg) {
        int ja = __shfl_sync(0xffffffffu, j1, i - 32);
        float wa = __shfl_sync(0xffffffffu, w1, i - 32);
        float4 va = *(const float4*)&hW[ja * DD + c];
        acc0.x = fmaf(wa, va.x, acc0.x); acc0.y = fmaf(wa, va.y, acc0.y);
        acc0.z = fmaf(wa, va.z, acc0.z); acc0.w = fmaf(wa, va.w, acc0.w);
    }

    float inv = __fdividef(1.f, ssum);
    acc0.x = (acc0.x + acc1.x) * inv;
    acc0.y = (acc0.y + acc1.y) * inv;
    acc0.z = (acc0.z + acc1.z) * inv;
    acc0.w = (acc0.w + acc1.w) * inv;

    float4 bv = *(const float4*)&bias[c];
    acc0.x = fmaxf(acc0.x + bv.x, 0.f);
    acc0.y = fmaxf(acc0.y + bv.y, 0.f);
    acc0.z = fmaxf(acc0.z + bv.z, 0.f);
    acc0.w = fmaxf(acc0.w + bv.w, 0.f);

    if (!doPool) {
        *(float4*)&g_h[node * DD + c] = acc0;
    } else {
        float4 ow = *(const float4*)&out_w[c];
        float s = acc0.x * ow.x + acc0.y * ow.y + acc0.z * ow.z + acc0.w * ow.w;
#pragma unroll
        for (int o = 16; o; o >>= 1)
            s += __shfl_xor_sync(0xffffffffu, s, o);
        if (lane == 0) {
            int b = batch[node];
            atomicAdd(&g_psum[b], s);
            atomicAdd(&g_cnt[b], 1.f);
        }
    }
}

// ---------------- final ----------------
__global__ void k_final(const float* __restrict__ out_b,
                        float* __restrict__ out) {
    int g = threadIdx.x;
    if (g < GG) out[g] = g_psum[g] / g_cnt[g] + out_b[0];
}

// ---------------- launch ----------------
extern "C" void kernel_launch(void* const* d_in, const int* in_sizes, int n_in,
                              void* d_out, int out_size) {
    const float* x     = (const float*)d_in[0];
    const int*   ei    = (const int*)d_in[1];
    const int*   batch = (const int*)d_in[2];
    const float* lin_w = (const float*)d_in[3];
    const float* lin_b = (const float*)d_in[4];
    const float* w1    = (const float*)d_in[5];
    const float* as1   = (const float*)d_in[6];
    const float* ad1   = (const float*)d_in[7];
    const float* b1    = (const float*)d_in[8];
    const float* w2    = (const float*)d_in[9];
    const float* as2   = (const float*)d_in[10];
    const float* ad2   = (const float*)d_in[11];
    const float* b2    = (const float*)d_in[12];
    const float* ow    = (const float*)d_in[13];
    const float* ob    = (const float*)d_in[14];
    float* out = (float*)d_out;

    const int* src = ei;
    const int* dst = ei + EE;

    static float* pC1 = nullptr;
    static float* pc1 = nullptr;
    static cudaStream_t sB = nullptr;
    static cudaEvent_t evFork = nullptr, evJoin = nullptr;
    static cudaEvent_t evA = nullptr, evB = nullptr;
    if (!pC1) {
        cudaGetSymbolAddress((void**)&pC1, g_C1);
        cudaGetSymbolAddress((void**)&pc1, g_c1);
        cudaStreamCreateWithFlags(&sB, cudaStreamNonBlocking);
        cudaEventCreateWithFlags(&evFork, cudaEventDisableTiming);
        cudaEventCreateWithFlags(&evJoin, cudaEventDisableTiming);
        cudaEventCreateWithFlags(&evA, cudaEventDisableTiming);
        cudaEventCreateWithFlags(&evB, cudaEventDisableTiming);
    }

    const int REM = NN - HSPLIT;                      // 24976
    int gemm_blocks_all = (NN + 31) / 32;             // 1563
    int gemm_blocks_c0  = HSPLIT / 32;                // 782
    int gemm_blocks_c1  = (REM + 31) / 32;            // 781
    int agg_blocks_c0   = HSPLIT / 8;                 // 3128
    int agg_blocks_c1   = (REM + 7) / 8;              // 3122
    int agg_blocks_all  = (NN + 7) / 8;               // 6250
    int edge_blocks = (EE + 255) / 256;

    // fork: fill runs concurrently with wfold + gemm1
    cudaEventRecord(evFork, 0);
    cudaStreamWaitEvent(sB, evFork, 0);
    k_fill<<<edge_blocks, 256, 0, sB>>>(src, dst);
    cudaEventRecord(evJoin, sB);

    k_wfold<<<65, 256>>>(lin_w, lin_b, w1);
    k_gemm<<<gemm_blocks_all, 128>>>(x, 1, pC1, pc1, 1, as1, ad1, 0, 0);

    // join fill, then agg1 chunk0
    cudaStreamWaitEvent(0, evJoin, 0);
    k_agg<<<agg_blocks_c0, 256>>>(b1, batch, 0, ow, 0, 0);
    cudaEventRecord(evA, 0);

    // agg1 chunk1 on sB  ∥  gemm2 chunk0 on main (disjoint g_h rows; bufB out)
    cudaStreamWaitEvent(sB, evA, 0);
    k_agg<<<agg_blocks_c1, 256, 0, sB>>>(b1, batch, 0, ow, HSPLIT, 0);
    cudaEventRecord(evB, sB);

    k_gemm<<<gemm_blocks_c0, 128>>>(nullptr, 0, w2, nullptr, 0, as2, ad2, 0, 1);

    // join, then gemm2 chunk1, agg2 (all), final
    cudaStreamWaitEvent(0, evB, 0);
    k_gemm<<<gemm_blocks_c1, 128>>>(nullptr, 0, w2, nullptr, 0, as2, ad2, HSPLIT, 1);
    k_agg<<<agg_blocks_all, 256>>>(b2, batch, 1, ow, 0, 1);
    k_final<<<1, GG>>>(ob, out);
}